// round 12
// baseline (speedup 1.0000x reference)
#include <cuda_runtime.h>
#include <cuda_bf16.h>

// out[n, d] = dist[n] * w[d]   (N = 1,000,000 rows, DIM = 256, fp32)
// R11 (resubmit of R9; previous runs died to container infra, kernel never ran):
// 256-bit streaming stores (st.global.cs.v8.f32, Blackwell sm_100a+) to halve
// LSU/L1 per-byte dispatch work on the store path. Grid-stride interleave
// (best empirical DRAM feed), 32-bit indices, one wave of 1184 CTAs x 256 thr
// pinned at 8 CTAs/SM. Fallback to 2x STG.128 if arch < sm_100.

#define DIM 256
#define V8_PER_ROW (DIM / 8)     // 32 x 32B chunks per row
#define TPB 256
#define NBLK 1184                // 148 SMs * 8 resident CTAs -> 1 wave
#define UNROLL 8

__device__ __forceinline__ void stcs_v8(float* p,
                                        const float4& a, const float4& b)
{
#if defined(__CUDA_ARCH__) && (__CUDA_ARCH__ >= 1000)
    asm volatile(
        "st.global.cs.v8.f32 [%0], {%1, %2, %3, %4, %5, %6, %7, %8};"
        :: "l"(p),
           "f"(a.x), "f"(a.y), "f"(a.z), "f"(a.w),
           "f"(b.x), "f"(b.y), "f"(b.z), "f"(b.w)
        : "memory");
#else
    __stcs(reinterpret_cast<float4*>(p),     a);
    __stcs(reinterpret_cast<float4*>(p) + 1, b);
#endif
}

__global__ __launch_bounds__(TPB, 8) void outer_product_v8(
    const float* __restrict__ dist,
    const float* __restrict__ weight,
    float* __restrict__ out,
    unsigned total_v8)           // n_rows * 32 = 32M < 2^32
{
    // Fixed 32B column chunk for this thread (grid stride is a mult of 32).
    const int col8 = threadIdx.x & (V8_PER_ROW - 1);
    const float4 w0 = __ldg(&reinterpret_cast<const float4*>(weight)[2 * col8]);
    const float4 w1 = __ldg(&reinterpret_cast<const float4*>(weight)[2 * col8 + 1]);

    const unsigned stride = NBLK * TPB;          // 303104 v8 units, mult of 32
    unsigned i = blockIdx.x * TPB + threadIdx.x;

    // Main loop: 8 interleaved rows per iteration, one STG.256 each.
    // i >> 5 = row; warp-uniform (warp spans exactly one row's 32 chunks).
    for (; i + (UNROLL - 1) * stride < total_v8; i += UNROLL * stride) {
        float d[UNROLL];
#pragma unroll
        for (int j = 0; j < UNROLL; j++) {
            d[j] = __ldg(&dist[(i + j * stride) >> 5]);
        }
#pragma unroll
        for (int j = 0; j < UNROLL; j++) {
            float4 r0, r1;
            r0.x = d[j] * w0.x; r0.y = d[j] * w0.y;
            r0.z = d[j] * w0.z; r0.w = d[j] * w0.w;
            r1.x = d[j] * w1.x; r1.y = d[j] * w1.y;
            r1.z = d[j] * w1.z; r1.w = d[j] * w1.w;
            stcs_v8(out + 8ull * (i + j * stride), r0, r1);
        }
    }

    // Tail.
    for (; i < total_v8; i += stride) {
        const float dd = __ldg(&dist[i >> 5]);
        float4 r0, r1;
        r0.x = dd * w0.x; r0.y = dd * w0.y; r0.z = dd * w0.z; r0.w = dd * w0.w;
        r1.x = dd * w1.x; r1.y = dd * w1.y; r1.z = dd * w1.z; r1.w = dd * w1.w;
        stcs_v8(out + 8ull * i, r0, r1);
    }
}

extern "C" void kernel_launch(void* const* d_in, const int* in_sizes, int n_in,
                              void* d_out, int out_size)
{
    const float* dist   = (const float*)d_in[0];
    const float* weight = (const float*)d_in[1];
    float* out          = (float*)d_out;

    unsigned total_v8 = (unsigned)in_sizes[0] * V8_PER_ROW;   // 32M

    outer_product_v8<<<NBLK, TPB>>>(dist, weight, out, total_v8);
}

// round 13
// speedup vs baseline: 1.0531x; 1.0531x over previous
#include <cuda_runtime.h>
#include <cuda_bf16.h>

// out[n, d] = dist[n] * w[d]   (N = 1,000,000 rows, DIM = 256, fp32)
// R12: verbatim re-bench of the R5 champion (158.5 us) to separate structure
// from DVFS noise. Single-wave persistent kernel, x8 unroll, streaming
// (evict-first) stores via __stcs. Each thread owns a fixed column (stride
// is a multiple of 64 vec4/row) -> weight float4 in registers; dist loads
// are warp-uniform broadcasts.

#define DIM 256
#define VEC4_PER_ROW (DIM / 4)   // 64
#define TPB 256
#define NBLK 1184                // 148 SMs * 8 resident CTAs -> 1 wave
#define UNROLL 8

__global__ __launch_bounds__(TPB) void outer_product_persistent(
    const float* __restrict__ dist,
    const float* __restrict__ weight,
    float4* __restrict__ out,
    int n_rows)
{
    const int col4 = threadIdx.x & (VEC4_PER_ROW - 1);
    const float4 w = __ldg(&reinterpret_cast<const float4*>(weight)[col4]);

    const long long stride = (long long)gridDim.x * TPB;        // multiple of 64
    const long long total  = (long long)n_rows * VEC4_PER_ROW;  // 64M vec4
    long long i = (long long)blockIdx.x * TPB + threadIdx.x;

    // Main loop: 8 rows per iteration. Front-batch the (warp-uniform) dist
    // loads, then compute+store each element immediately so register live
    // ranges stay short.
    for (; i + (UNROLL - 1) * stride < total; i += (long long)UNROLL * stride) {
        float d[UNROLL];
#pragma unroll
        for (int j = 0; j < UNROLL; j++) {
            d[j] = __ldg(&dist[(int)((i + j * stride) >> 6)]);
        }
#pragma unroll
        for (int j = 0; j < UNROLL; j++) {
            float4 r;
            r.x = d[j] * w.x;
            r.y = d[j] * w.y;
            r.z = d[j] * w.z;
            r.w = d[j] * w.w;
            __stcs(&out[i + j * stride], r);   // evict-first streaming store
        }
    }

    // Tail.
    for (; i < total; i += stride) {
        const float dd = __ldg(&dist[(int)(i >> 6)]);
        float4 r;
        r.x = dd * w.x; r.y = dd * w.y; r.z = dd * w.z; r.w = dd * w.w;
        __stcs(&out[i], r);
    }
}

extern "C" void kernel_launch(void* const* d_in, const int* in_sizes, int n_in,
                              void* d_out, int out_size)
{
    const float* dist   = (const float*)d_in[0];
    const float* weight = (const float*)d_in[1];
    float4* out         = (float4*)d_out;

    int n_rows = in_sizes[0];   // 1,000,000

    outer_product_persistent<<<NBLK, TPB>>>(dist, weight, out, n_rows);
}